// round 2
// baseline (speedup 1.0000x reference)
#include <cuda_runtime.h>
#include <cuda_bf16.h>

// Problem constants (fixed by the reference setup)
#define B_  2
#define L_  24
#define C_  16
#define H_  64
#define W_  64
#define HW_ 4096

// Channel-last scratch copy of images: [B, L, H, W, C] (each pixel = 16
// contiguous floats = 64 bytes, so every bilinear tap is 4x LDG.128).
__device__ float g_imgT[(size_t)B_ * L_ * HW_ * C_];

// NCHW -> NHWC transpose. One thread per (b,l,pixel); gathers 16 channel
// values (coalesced across pix for each c) and writes 4x STG.128.
__global__ __launch_bounds__(256) void transpose_kernel(
    const float* __restrict__ images)
{
    const int pix = blockIdx.x * blockDim.x + threadIdx.x;   // 0..4095
    const int bl  = blockIdx.y;                              // 0..47
    const float* src = images + (size_t)bl * C_ * HW_ + pix;
    float4* dst = (float4*)(g_imgT + ((size_t)bl * HW_ + pix) * C_);

    float v[C_];
#pragma unroll
    for (int c = 0; c < C_; ++c) v[c] = src[(size_t)c * HW_];
#pragma unroll
    for (int j = 0; j < 4; ++j)
        dst[j] = make_float4(v[4*j], v[4*j+1], v[4*j+2], v[4*j+3]);
}

// out[b,t,c,h,w] = sum_{k<=t} bilinear_sample( images[b,k,c],
//    grid = pixel_center(h,w) + 32*(cumflow[t]-cumflow[k]) )
// x wrapped into [-0.5, 63.5), zeros padding at borders.
// One thread per (b,t,h,w); relative flow telescopes (accumulated on the fly).
__global__ __launch_bounds__(128) void gsp_kernel(
    const float* __restrict__ flows,    // [B, L, 2, H, W]
    float* __restrict__ out)            // [B, L, C, H, W]
{
    const int b   = blockIdx.z;
    const int t   = (L_ - 1) - blockIdx.y;   // longest blocks launch first
    const int pix = blockIdx.x * blockDim.x + threadIdx.x;   // 0..4095
    const int h   = pix >> 6;
    const int w   = pix & 63;

    float4 acc[4];
#pragma unroll
    for (int j = 0; j < 4; ++j) acc[j] = make_float4(0.f, 0.f, 0.f, 0.f);

    float relx = 0.f, rely = 0.f;
    const float* flowbase = flows + (size_t)b * L_ * 2 * HW_ + pix;

    for (int k = t; k >= 0; --k) {
        if (k < t) {
            // rel(k) = rel(k+1) + flow[k+1]
            const float* fp = flowbase + (size_t)(k + 1) * 2 * HW_;
            relx += fp[0];
            rely += fp[HW_];
        }

        // sample coordinate (align_corners=False): base grid == pixel centers
        float ix = (float)w + 32.f * relx;
        ix -= 64.f * floorf((ix + 0.5f) * 0.015625f);   // wrap x into [-0.5, 63.5)
        float iy = (float)h + 32.f * rely;

        float x0f = floorf(ix), y0f = floorf(iy);
        int   x0  = (int)x0f,   y0  = (int)y0f;
        float wx1 = ix - x0f,   wy1 = iy - y0f;
        float wx0 = 1.f - wx1,  wy0 = 1.f - wy1;

        // x0 in [-1, 63] by construction; x1 = x0+1 in [0, 64]
        bool vx0 = (x0 >= 0);
        bool vx1 = (x0 < W_ - 1);
        bool vy0 = (y0 >= 0) && (y0 <= H_ - 1);
        bool vy1 = (y0 >= -1) && (y0 < H_ - 1);

        float w00 = wx0 * wy0 * (float)(vx0 && vy0);
        float w01 = wx1 * wy0 * (float)(vx1 && vy0);
        float w10 = wx0 * wy1 * (float)(vx0 && vy1);
        float w11 = wx1 * wy1 * (float)(vx1 && vy1);

        int cx0 = max(x0, 0),              cx1 = min(x0 + 1, W_ - 1);
        int cy0 = min(max(y0, 0), H_ - 1), cy1 = min(max(y0 + 1, 0), H_ - 1);

        const float4* ib = (const float4*)(g_imgT + ((size_t)b * L_ + k) * HW_ * C_);
        const float4* p00 = ib + (size_t)(cy0 * W_ + cx0) * 4;
        const float4* p01 = ib + (size_t)(cy0 * W_ + cx1) * 4;
        const float4* p10 = ib + (size_t)(cy1 * W_ + cx0) * 4;
        const float4* p11 = ib + (size_t)(cy1 * W_ + cx1) * 4;

#pragma unroll
        for (int j = 0; j < 4; ++j) {
            float4 v00 = p00[j], v01 = p01[j], v10 = p10[j], v11 = p11[j];
            acc[j].x += w00 * v00.x + w01 * v01.x + w10 * v10.x + w11 * v11.x;
            acc[j].y += w00 * v00.y + w01 * v01.y + w10 * v10.y + w11 * v11.y;
            acc[j].z += w00 * v00.z + w01 * v01.z + w10 * v10.z + w11 * v11.z;
            acc[j].w += w00 * v00.w + w01 * v01.w + w10 * v10.w + w11 * v11.w;
        }
    }

    // out layout is NCHW: 16 strided coalesced stores
    float* op = out + ((size_t)b * L_ + t) * C_ * HW_ + pix;
#pragma unroll
    for (int j = 0; j < 4; ++j) {
        op[(4*j+0) * HW_] = acc[j].x;
        op[(4*j+1) * HW_] = acc[j].y;
        op[(4*j+2) * HW_] = acc[j].z;
        op[(4*j+3) * HW_] = acc[j].w;
    }
}

extern "C" void kernel_launch(void* const* d_in, const int* in_sizes, int n_in,
                              void* d_out, int out_size)
{
    const float* flows  = (const float*)d_in[0];   // [2,24,2,64,64]
    const float* images = (const float*)d_in[1];   // [2,24,16,64,64]
    float*       out    = (float*)d_out;           // [2,24,16,64,64]

    dim3 tgrid(HW_ / 256, B_ * L_);                // (16, 48)
    transpose_kernel<<<tgrid, 256>>>(images);

    dim3 grid(HW_ / 128, L_, B_);                  // (32, 24, 2)
    gsp_kernel<<<grid, 128>>>(flows, out);
}

// round 3
// speedup vs baseline: 1.5955x; 1.5955x over previous
#include <cuda_runtime.h>
#include <cuda_bf16.h>

#define B_  2
#define L_  24
#define C_  16
#define H_  64
#define W_  64
#define HW_ 4096

// Cumulative flow scratch: [B][L][HW] float2 (x,y interleaved per pixel).
__device__ float2 g_cum[(size_t)B_ * L_ * HW_];

// cum[b,k,pix] = sum_{j<=k} flows[b,j,:,pix].  Thread per (b,pix), serial in k.
__global__ __launch_bounds__(256) void cum_kernel(
    const float* __restrict__ flows)    // [B, L, 2, H, W]
{
    const int pix = blockIdx.x * blockDim.x + threadIdx.x;   // 0..4095
    const int b   = blockIdx.y;
    const float* fp = flows + (size_t)b * L_ * 2 * HW_ + pix;
    float2* cp = g_cum + (size_t)b * L_ * HW_ + pix;

    float sx = 0.f, sy = 0.f;
#pragma unroll
    for (int k = 0; k < L_; ++k) {
        sx += fp[(size_t)k * 2 * HW_];
        sy += fp[(size_t)k * 2 * HW_ + HW_];
        cp[(size_t)k * HW_] = make_float2(sx, sy);
    }
}

// out[b,t,c,h,w] = sum_{k<=t} bilinear_sample(images[b,k,c],
//     pixel_center(h,w) + 32*(cum[t]-cum[k])),
// x wrapped into [-0.5, 63.5), zeros padding at borders.
// Thread = (b, t, half, pixel) handling 8 channels; k-iterations independent
// (cum precomputed) so the compiler can overlap tap batches across k.
__global__ __launch_bounds__(256) void gsp_kernel(
    const float* __restrict__ images,   // [B, L, C, H, W]
    float* __restrict__ out)            // [B, L, C, H, W]
{
    const int b    = blockIdx.z >> 1;
    const int half = blockIdx.z & 1;          // channel half: 0 -> c0..7, 1 -> c8..15
    const int t    = (L_ - 1) - blockIdx.y;   // longest-running t launches first
    const int pix  = blockIdx.x * blockDim.x + threadIdx.x;   // 0..4095
    const int h    = pix >> 6;
    const int w    = pix & 63;

    float acc[8];
#pragma unroll
    for (int c = 0; c < 8; ++c) acc[c] = 0.f;

    const float2* cumb = g_cum + (size_t)b * L_ * HW_ + pix;
    const float2 cumt = cumb[(size_t)t * HW_];
    const float* imgb = images + ((size_t)b * L_) * C_ * HW_ + (size_t)half * 8 * HW_;

#pragma unroll 2
    for (int k = 0; k <= t; ++k) {
        float relx, rely;
        if (k == t) { relx = 0.f; rely = 0.f; }
        else {
            const float2 ck = cumb[(size_t)k * HW_];
            relx = cumt.x - ck.x;
            rely = cumt.y - ck.y;
        }

        // align_corners=False: base grid == pixel centers
        float ix = (float)w + 32.f * relx;
        ix -= 64.f * floorf((ix + 0.5f) * 0.015625f);   // wrap x into [-0.5, 63.5)
        float iy = (float)h + 32.f * rely;

        float x0f = floorf(ix), y0f = floorf(iy);
        int   x0  = (int)x0f,   y0  = (int)y0f;
        float wx1 = ix - x0f,   wy1 = iy - y0f;
        float wx0 = 1.f - wx1,  wy0 = 1.f - wy1;

        // x0 in [-1, 63] by construction; x1 = x0+1 in [0, 64]
        bool vx0 = (x0 >= 0);
        bool vx1 = (x0 < W_ - 1);
        bool vy0 = (y0 >= 0) && (y0 <= H_ - 1);
        bool vy1 = (y0 >= -1) && (y0 < H_ - 1);

        float w00 = wx0 * wy0 * (float)(vx0 && vy0);
        float w01 = wx1 * wy0 * (float)(vx1 && vy0);
        float w10 = wx0 * wy1 * (float)(vx0 && vy1);
        float w11 = wx1 * wy1 * (float)(vx1 && vy1);

        int cx0 = max(x0, 0),              cx1 = min(x0 + 1, W_ - 1);
        int cy0 = min(max(y0, 0), H_ - 1), cy1 = min(max(y0 + 1, 0), H_ - 1);

        const int o00 = cy0 * W_ + cx0, o01 = cy0 * W_ + cx1;
        const int o10 = cy1 * W_ + cx0, o11 = cy1 * W_ + cx1;

        const float* ib = imgb + (size_t)k * C_ * HW_;
#pragma unroll
        for (int c = 0; c < 8; ++c) {
            const float* p = ib + (size_t)c * HW_;
            acc[c] += w00 * p[o00] + w01 * p[o01] + w10 * p[o10] + w11 * p[o11];
        }
    }

    float* op = out + (((size_t)b * L_ + t) * C_ + half * 8) * HW_ + pix;
#pragma unroll
    for (int c = 0; c < 8; ++c) op[(size_t)c * HW_] = acc[c];
}

extern "C" void kernel_launch(void* const* d_in, const int* in_sizes, int n_in,
                              void* d_out, int out_size)
{
    const float* flows  = (const float*)d_in[0];   // [2,24,2,64,64]
    const float* images = (const float*)d_in[1];   // [2,24,16,64,64]
    float*       out    = (float*)d_out;           // [2,24,16,64,64]

    dim3 cgrid(HW_ / 256, B_);                     // (16, 2)
    cum_kernel<<<cgrid, 256>>>(flows);

    dim3 grid(HW_ / 256, L_, B_ * 2);              // (16, 24, 4)
    gsp_kernel<<<grid, 256>>>(images, out);
}

// round 4
// speedup vs baseline: 1.7117x; 1.0728x over previous
#include <cuda_runtime.h>
#include <cuda_bf16.h>

#define B_  2
#define L_  24
#define C_  16
#define H_  64
#define W_  64
#define HW_ 4096
#define KCH 6

// Cumulative flow scratch: [B][L][HW] float2 (x,y interleaved per pixel).
__device__ float2 g_cum[(size_t)B_ * L_ * HW_];

// (t, k0) chunk table: for each t, chunks of <=KCH k-values. 60 entries.
__constant__ short2 g_chunks[60] = {
    {0,0},{1,0},{2,0},{3,0},{4,0},{5,0},
    {6,0},{6,6},{7,0},{7,6},{8,0},{8,6},{9,0},{9,6},{10,0},{10,6},{11,0},{11,6},
    {12,0},{12,6},{12,12},{13,0},{13,6},{13,12},{14,0},{14,6},{14,12},
    {15,0},{15,6},{15,12},{16,0},{16,6},{16,12},{17,0},{17,6},{17,12},
    {18,0},{18,6},{18,12},{18,18},{19,0},{19,6},{19,12},{19,18},
    {20,0},{20,6},{20,12},{20,18},{21,0},{21,6},{21,12},{21,18},
    {22,0},{22,6},{22,12},{22,18},{23,0},{23,6},{23,12},{23,18}
};

// Zero the output (it is poisoned before timing; gsp accumulates atomically).
__global__ __launch_bounds__(256) void zero_kernel(float4* __restrict__ out, int n4)
{
    int i = blockIdx.x * blockDim.x + threadIdx.x;
    if (i < n4) out[i] = make_float4(0.f, 0.f, 0.f, 0.f);
}

// cum[b,k,pix] = sum_{j<=k} flows[b,j,:,pix].  Thread per (b,pix), serial in k.
__global__ __launch_bounds__(256) void cum_kernel(
    const float* __restrict__ flows)    // [B, L, 2, H, W]
{
    const int pix = blockIdx.x * blockDim.x + threadIdx.x;   // 0..4095
    const int b   = blockIdx.y;
    const float* fp = flows + (size_t)b * L_ * 2 * HW_ + pix;
    float2* cp = g_cum + (size_t)b * L_ * HW_ + pix;

    float sx = 0.f, sy = 0.f;
#pragma unroll
    for (int k = 0; k < L_; ++k) {
        sx += fp[(size_t)k * 2 * HW_];
        sy += fp[(size_t)k * 2 * HW_ + HW_];
        cp[(size_t)k * HW_] = make_float2(sx, sy);
    }
}

// out[b,t,c,h,w] += sum_{k in chunk} bilinear_sample(images[b,k,c],
//     pixel_center(h,w) + 32*(cum[t]-cum[k])),
// x wrapped into [-0.5, 63.5), zeros padding at borders.
// Block = (pixtile, chunk, b*2+half); every block does <= KCH k-iterations
// so block durations are near-uniform (no long-t drain tail).
__global__ __launch_bounds__(256) void gsp_kernel(
    const float* __restrict__ images,   // [B, L, C, H, W]
    float* __restrict__ out)            // [B, L, C, H, W]
{
    const int b    = blockIdx.z >> 1;
    const int half = blockIdx.z & 1;          // channel half: 0 -> c0..7, 1 -> c8..15
    const short2 ck_ = g_chunks[blockIdx.y];
    const int t    = ck_.x;
    const int k0   = ck_.y;
    const int kend = min(k0 + KCH, t + 1);
    const int pix  = blockIdx.x * blockDim.x + threadIdx.x;   // 0..4095
    const int h    = pix >> 6;
    const int w    = pix & 63;

    float acc[8];
#pragma unroll
    for (int c = 0; c < 8; ++c) acc[c] = 0.f;

    const float2* cumb = g_cum + (size_t)b * L_ * HW_ + pix;
    const float2 cumt = cumb[(size_t)t * HW_];
    const float* imgb = images + ((size_t)b * L_) * C_ * HW_ + (size_t)half * 8 * HW_;

#pragma unroll 3
    for (int k = k0; k < kend; ++k) {
        const float2 ckf = cumb[(size_t)k * HW_];
        float relx = cumt.x - ckf.x;   // exactly 0 when k==t
        float rely = cumt.y - ckf.y;

        // align_corners=False: base grid == pixel centers
        float ix = (float)w + 32.f * relx;
        ix -= 64.f * floorf((ix + 0.5f) * 0.015625f);   // wrap x into [-0.5, 63.5)
        float iy = (float)h + 32.f * rely;

        float x0f = floorf(ix), y0f = floorf(iy);
        int   x0  = (int)x0f,   y0  = (int)y0f;
        float wx1 = ix - x0f,   wy1 = iy - y0f;
        float wx0 = 1.f - wx1,  wy0 = 1.f - wy1;

        // x0 in [-1, 63] by construction; x1 = x0+1 in [0, 64]
        bool vx0 = (x0 >= 0);
        bool vx1 = (x0 < W_ - 1);
        bool vy0 = (y0 >= 0) && (y0 <= H_ - 1);
        bool vy1 = (y0 >= -1) && (y0 < H_ - 1);

        float w00 = wx0 * wy0 * (float)(vx0 && vy0);
        float w01 = wx1 * wy0 * (float)(vx1 && vy0);
        float w10 = wx0 * wy1 * (float)(vx0 && vy1);
        float w11 = wx1 * wy1 * (float)(vx1 && vy1);

        int cx0 = max(x0, 0),              cx1 = min(x0 + 1, W_ - 1);
        int cy0 = min(max(y0, 0), H_ - 1), cy1 = min(max(y0 + 1, 0), H_ - 1);

        const int o00 = cy0 * W_ + cx0, o01 = cy0 * W_ + cx1;
        const int o10 = cy1 * W_ + cx0, o11 = cy1 * W_ + cx1;

        const float* ib = imgb + (size_t)k * C_ * HW_;
#pragma unroll
        for (int c = 0; c < 8; ++c) {
            const float* p = ib + (size_t)c * HW_;
            acc[c] += w00 * p[o00] + w01 * p[o01] + w10 * p[o10] + w11 * p[o11];
        }
    }

    float* op = out + (((size_t)b * L_ + t) * C_ + half * 8) * HW_ + pix;
#pragma unroll
    for (int c = 0; c < 8; ++c) atomicAdd(op + (size_t)c * HW_, acc[c]);
}

extern "C" void kernel_launch(void* const* d_in, const int* in_sizes, int n_in,
                              void* d_out, int out_size)
{
    const float* flows  = (const float*)d_in[0];   // [2,24,2,64,64]
    const float* images = (const float*)d_in[1];   // [2,24,16,64,64]
    float*       out    = (float*)d_out;           // [2,24,16,64,64]

    int n4 = out_size / 4;                         // 196608 float4s
    zero_kernel<<<(n4 + 255) / 256, 256>>>((float4*)out, n4);

    dim3 cgrid(HW_ / 256, B_);                     // (16, 2)
    cum_kernel<<<cgrid, 256>>>(flows);

    dim3 grid(HW_ / 256, 60, B_ * 2);              // (16, 60, 4)
    gsp_kernel<<<grid, 256>>>(images, out);
}